// round 12
// baseline (speedup 1.0000x reference)
#include <cuda_runtime.h>
#include <cuda_bf16.h>
#include <cstdint>

// NnInteractionTokenizer: bond = x[row]*x[col]; local_field = segsum(bond, row);
// tokens = relu(relu([x, lf] @ w1^T + b1) @ w2^T + b2)
//
// local_field[r] = x[r] * sum_{e: row[e]=r} x[col[e]] -> edge phase only
// accumulates x[col[e]] into g_acc[row[e]]; x[r] multiply folds into node phase.
//
// Edge kernel (UNCHANGED, measured ~50us = L1tex wavefront + REDG floor):
// 256thr/8CTA -> 64 warps/SM. Node kernel: TPN=2 threads/node (+parallelism),
// warp-local read->clear of g_acc (no block barrier), and PDL so its prologue
// overlaps the edge kernel's tail wave.
//
// g_acc invariant: __device__ globals start zeroed; node phase re-zeroes each
// g_acc[n] after both readers (same warp) have read it -> zero at every replay.

#define N_NODES 100000
#define N_EDGES 6400000
#define TD 16
#define EPT 4

__device__ float g_acc[N_NODES];

// ---------------------------------------------------------------------------
// Edge phase: EPT edges/thread; vectorized index loads (DRAM stream), batched
// divergent gathers (L1/L2), EPT fire-and-forget REDG.F32 into g_acc.
//
// Dtype probe (per block, uniform): reference asks int64 but JAX w/o x64
// yields int32 (confirmed: measured HBM traffic ~51MB). As uint32 words,
// int64 data (<2^17, LE) has odd words == 0; int32 data has random words ->
// P(8 specific odd words all zero) ~ 1e-40. All blocks read the SAME 8 words
// (L2 broadcast) -> globally uniform decision.
// ---------------------------------------------------------------------------
__global__ void __launch_bounds__(256, 8) edge_kernel(const void* __restrict__ ei,
                                                      const float* __restrict__ x) {
#if (__CUDACC_VER_MAJOR__ >= 12)
    cudaTriggerProgrammaticLaunchCompletion();   // fires when last wave is resident
#endif
    __shared__ int s_is64;
    if (threadIdx.x == 0) {
        const unsigned int* w = (const unsigned int*)ei;
        unsigned int acc = 0;
#pragma unroll
        for (int k = 0; k < 8; k++) acc |= w[2 * k + 1];
        s_is64 = (acc == 0u) ? 1 : 0;
    }
    __syncthreads();

    const int tid = blockIdx.x * blockDim.x + threadIdx.x;
    const long long base = (long long)tid * EPT;
    if (base >= N_EDGES) return;

    if (!s_is64) {
        // int32 path (the measured-real one): kept lean for <=32 regs.
        const int4* row = (const int4*)ei;
        const int4* col = row + (N_EDGES / 4);
        int4 rv = __ldg(&row[base / 4]);
        int4 cv = __ldg(&col[base / 4]);

        float v0 = __ldg(&x[cv.x]);
        float v1 = __ldg(&x[cv.y]);
        float v2 = __ldg(&x[cv.z]);
        float v3 = __ldg(&x[cv.w]);

        atomicAdd(&g_acc[rv.x], v0);
        atomicAdd(&g_acc[rv.y], v1);
        atomicAdd(&g_acc[rv.z], v2);
        atomicAdd(&g_acc[rv.w], v3);
    } else {
        const longlong2* row = (const longlong2*)ei;          // edge_index[0]
        const longlong2* col = row + (N_EDGES / 2);           // edge_index[1]
        longlong2 r0 = __ldg(&row[base / 2]);
        longlong2 r1 = __ldg(&row[base / 2 + 1]);
        longlong2 c0 = __ldg(&col[base / 2]);
        longlong2 c1 = __ldg(&col[base / 2 + 1]);

        float v0 = __ldg(&x[(int)c0.x]);
        float v1 = __ldg(&x[(int)c0.y]);
        float v2 = __ldg(&x[(int)c1.x]);
        float v3 = __ldg(&x[(int)c1.y]);

        atomicAdd(&g_acc[(int)r0.x], v0);
        atomicAdd(&g_acc[(int)r0.y], v1);
        atomicAdd(&g_acc[(int)r1.x], v2);
        atomicAdd(&g_acc[(int)r1.y], v3);
    }
}

// ---------------------------------------------------------------------------
// Node phase: 2->16->16 MLP, TWO threads per node (even lane: outputs 0-7,
// odd lane: outputs 8-15). Layer-1 (32 FMA) duplicated — cheap. g_acc
// read->clear ordered by __syncwarp (pair shares a warp), no block barrier.
// PDL: prologue (weights + x load) runs before cudaGridDependencySynchronize,
// overlapping the edge kernel's tail; g_acc is only touched after the sync.
// ---------------------------------------------------------------------------
__global__ void __launch_bounds__(256) node_kernel(const float* __restrict__ x,
                                                   const float* __restrict__ w1,
                                                   const float* __restrict__ b1,
                                                   const float* __restrict__ w2,
                                                   const float* __restrict__ b2,
                                                   float* __restrict__ out) {
    __shared__ float sw1[2 * TD];
    __shared__ float sb1[TD];
    __shared__ __align__(16) float sw2[TD * TD];
    __shared__ float sb2[TD];

    const int t = threadIdx.x;
    const int g = blockIdx.x * 256 + t;
    const int n = g >> 1;           // node index
    const int half = g & 1;         // which 8 outputs
    const bool act = (n < N_NODES);

    // Prologue (no g_acc access): overlaps edge tail under PDL.
    if (t < 2 * TD) sw1[t] = w1[t];
    if (t < TD) { sb1[t] = b1[t]; sb2[t] = b2[t]; }
    sw2[t] = w2[t];   // blockDim == 256 == TD*TD
    float s = 0.f;
    if (act) s = x[n];
    __syncthreads();

#if (__CUDACC_VER_MAJOR__ >= 12)
    cudaGridDependencySynchronize();   // edge results now visible
#endif

    float lfa = 0.f;
    if (act) lfa = g_acc[n];
    __syncwarp();                       // both readers of node n done
    if (act && half == 0) g_acc[n] = 0.0f;   // clear for next replay

    const float lf = s * lfa;

    // Layer 1 (duplicated across the pair): h = relu(s*w1[:,0] + lf*w1[:,1] + b1)
    float h[TD];
#pragma unroll
    for (int j = 0; j < TD; j++) {
        float v = fmaf(sw1[2 * j + 1], lf, fmaf(sw1[2 * j], s, sb1[j]));
        h[j] = v > 0.f ? v : 0.f;
    }

    // Layer 2: this thread's 8 outputs k = half*8 .. half*8+7 (LDS.128 weights)
    float4* o = (float4*)(out + (size_t)n * TD) + half * 2;
#pragma unroll
    for (int k4 = 0; k4 < 2; k4++) {
        float4 res;
        float* rp = (float*)&res;
#pragma unroll
        for (int kk = 0; kk < 4; kk++) {
            const int k = half * 8 + k4 * 4 + kk;
            float v = sb2[k];
            const float4* wrow = (const float4*)&sw2[k * TD];
#pragma unroll
            for (int j4 = 0; j4 < 4; j4++) {
                float4 w = wrow[j4];
                v = fmaf(w.x, h[j4 * 4 + 0], v);
                v = fmaf(w.y, h[j4 * 4 + 1], v);
                v = fmaf(w.z, h[j4 * 4 + 2], v);
                v = fmaf(w.w, h[j4 * 4 + 3], v);
            }
            rp[kk] = v > 0.f ? v : 0.f;
        }
        if (act) o[k4] = res;
    }
}

extern "C" void kernel_launch(void* const* d_in, const int* in_sizes, int n_in,
                              void* d_out, int out_size) {
    const float* x  = (const float*)d_in[0];
    const void*  ei = d_in[1];
    const float* w1 = (const float*)d_in[2];
    const float* b1 = (const float*)d_in[3];
    const float* w2 = (const float*)d_in[4];
    const float* b2 = (const float*)d_in[5];
    float* out = (float*)d_out;

    edge_kernel<<<N_EDGES / EPT / 256, 256>>>(ei, x);

    // Node launch with PDL attribute (overlap prologue with edge tail).
    cudaLaunchConfig_t cfg = {};
    cfg.gridDim  = dim3((N_NODES * 2 + 255) / 256, 1, 1);
    cfg.blockDim = dim3(256, 1, 1);
    cudaLaunchAttribute attr[1];
    attr[0].id = cudaLaunchAttributeProgrammaticStreamSerialization;
    attr[0].val.programmaticStreamSerializationAllowed = 1;
    cfg.attrs = attr;
    cfg.numAttrs = 1;
    cudaLaunchKernelEx(&cfg, node_kernel, x, w1, b1, w2, b2, out);
}